// round 1
// baseline (speedup 1.0000x reference)
#include <cuda_runtime.h>
#include <math.h>

// Problem shape (fixed by reference setup_inputs)
#define BATCH 2048
#define NLABELS 50000
#define NTRIALS 64

#define WARPS_PER_BLOCK 8
#define THREADS_PER_BLOCK (WARPS_PER_BLOCK * 32)
#define NUM_BLOCKS (BATCH / WARPS_PER_BLOCK)   // 256

// Scratch for deterministic two-stage reduction (no allocations allowed).
__device__ float g_partials[NUM_BLOCKS];

// One warp per batch row. Lane l handles trials l (first ballot) and l+32
// (second ballot); __ffs on the ballot gives the FIRST accepted trial.
__global__ void __launch_bounds__(THREADS_PER_BLOCK)
warp_loss_main(const float* __restrict__ inp,
               const int* __restrict__ pos_idx,
               const int* __restrict__ neg_cands)
{
    const int lane = threadIdx.x & 31;
    const int wid_in_blk = threadIdx.x >> 5;
    const int row = blockIdx.x * WARPS_PER_BLOCK + wid_in_blk;

    float loss = 0.0f;

    {
        const long base = (long)row * NLABELS;
        const int p = __ldg(pos_idx + row);                    // broadcast load
        const float pos_s = __ldg(inp + base + p);             // same addr all lanes

        const int* nc = neg_cands + row * NTRIALS;
        const int i0 = __ldg(nc + lane);
        const int i1 = __ldg(nc + lane + 32);
        const float n0 = __ldg(inp + base + i0);               // independent gathers
        const float n1 = __ldg(inp + base + i1);

        const float thr = pos_s - 1.0f;                        // margin>=0 <=> neg>=pos-1
        const unsigned m0 = __ballot_sync(0xffffffffu, n0 >= thr);
        const unsigned m1 = __ballot_sync(0xffffffffu, n1 >= thr);

        if (m0 | m1) {
            int first;
            float sel;
            if (m0) {
                const int l = __ffs(m0) - 1;
                first = l;
                sel = __shfl_sync(0xffffffffu, n0, l);
            } else {
                const int l = __ffs(m1) - 1;
                first = 32 + l;
                sel = __shfl_sync(0xffffffffu, n1, l);
            }
            const float nt = (float)(first + 1);
            const float L = logf(floorf((float)(NLABELS - 1) / nt));
            loss = L * (1.0f - pos_s + sel);
        }
    }

    // Per-block deterministic reduction: every lane in a warp holds the same
    // loss value; lane 0 deposits it, thread 0 sums the 8 warps.
    __shared__ float s_loss[WARPS_PER_BLOCK];
    if (lane == 0) s_loss[wid_in_blk] = loss;
    __syncthreads();
    if (threadIdx.x == 0) {
        float sum = 0.0f;
        #pragma unroll
        for (int i = 0; i < WARPS_PER_BLOCK; i++) sum += s_loss[i];
        g_partials[blockIdx.x] = sum;
    }
}

// Deterministic tree reduction of 256 block partials -> d_out[0].
__global__ void __launch_bounds__(NUM_BLOCKS)
warp_loss_reduce(float* __restrict__ out)
{
    __shared__ float s[NUM_BLOCKS];
    const int t = threadIdx.x;
    s[t] = g_partials[t];
    __syncthreads();
    #pragma unroll
    for (int stride = NUM_BLOCKS / 2; stride >= 1; stride >>= 1) {
        if (t < stride) s[t] += s[t + stride];
        __syncthreads();
    }
    if (t == 0) out[0] = s[0];
}

extern "C" void kernel_launch(void* const* d_in, const int* in_sizes, int n_in,
                              void* d_out, int out_size)
{
    // metadata order: input (f32 [B,Y]), target (i32, UNUSED), pos_idx (i32 [B]),
    //                 neg_cands (i32 [B,T]); output f32 [1]
    const float* inp      = (const float*)d_in[0];
    const int*   pos_idx  = (const int*)d_in[2];
    const int*   neg      = (const int*)d_in[3];
    float*       out      = (float*)d_out;

    warp_loss_main<<<NUM_BLOCKS, THREADS_PER_BLOCK>>>(inp, pos_idx, neg);
    warp_loss_reduce<<<1, NUM_BLOCKS>>>(out);
}